// round 14
// baseline (speedup 1.0000x reference)
#include <cuda_runtime.h>
#include <cstdint>
#include <cstddef>

#define NB 16
#define NS 2048
#define ND 1024
#define NM 256
#define NROWS (NB*NS)   // 32768

// ---------------- scratch (device globals: allocation-free) ----------------
__device__ __align__(16) float g_xf[(size_t)NROWS * NM];
__device__ __align__(16) float g_xu[(size_t)NROWS * NM];
__device__ __align__(16) float g_xm[(size_t)NROWS * NM];
__device__ __align__(16) float g_H [(size_t)NROWS * NM];
__device__ int g_prog [256];   // proj progress: row-block (b*16+c), target 6
__device__ int g_hprog[256];   // H progress: row-block (b*16+c), target 4

// ---------------- dynamic smem layout ----------------
// GEMM pair-blocks: As[2][128][20] @0 (20480B), Bs halves @20480/@40960
// Recurrence: h[4][256] @0 (4096B: A0,A1,B0,B1), mbar[4] @4096
#define DSM_AS    0
#define DSM_BS    20480
#define DSM_TOTAL 61440

// ---------------- helpers ----------------
__device__ __forceinline__ uint32_t f2tf32(float x) {
    uint32_t r; asm("cvt.rna.tf32.f32 %0, %1;" : "=r"(r) : "f"(x)); return r;
}
__device__ __forceinline__ void mma_tf32(float c[4], const uint32_t a[4], const uint32_t b[2]) {
    asm volatile("mma.sync.aligned.m16n8k8.row.col.f32.tf32.tf32.f32 "
        "{%0,%1,%2,%3}, {%4,%5,%6,%7}, {%8,%9}, {%0,%1,%2,%3};"
        : "+f"(c[0]), "+f"(c[1]), "+f"(c[2]), "+f"(c[3])
        : "r"(a[0]), "r"(a[1]), "r"(a[2]), "r"(a[3]), "r"(b[0]), "r"(b[1]));
}
__device__ __forceinline__ uint32_t smem_u32(const void* p) {
    return (uint32_t)__cvta_generic_to_shared(p);
}
__device__ __forceinline__ unsigned long long pack2(float lo, float hi) {
    unsigned long long r;
    asm("mov.b64 %0, {%1, %2};" : "=l"(r) : "f"(lo), "f"(hi));
    return r;
}
__device__ __forceinline__ void unpack2(float& lo, float& hi, unsigned long long v) {
    asm("mov.b64 {%0, %1}, %2;" : "=f"(lo), "=f"(hi) : "l"(v));
}
#define FFMA2(acc, a, b) \
    asm("fma.rn.f32x2 %0, %1, %2, %0;" : "+l"(acc) : "l"(a), "l"(b))

#define CLUSTER_SYNC_() do {                                          \
    asm volatile("barrier.cluster.arrive.aligned;" ::: "memory");     \
    asm volatile("barrier.cluster.wait.aligned;"   ::: "memory");     \
} while (0)

#define MBAR_INIT(addr, cnt) \
    asm volatile("mbarrier.init.shared.b64 [%0], %1;" :: "r"(addr), "r"(cnt) : "memory")

#define MBAR_WAIT_CL(addr, par) do {                                         \
    uint32_t _m = (addr); uint32_t _p = (par); uint32_t _done;               \
    asm volatile(                                                            \
        "{\n\t.reg .pred p;\n\t"                                             \
        "mbarrier.try_wait.parity.acquire.cluster.shared::cta.b64 p, [%1], %2;\n\t" \
        "selp.b32 %0, 1, 0, p;\n\t}"                                         \
        : "=r"(_done) : "r"(_m), "r"(_p) : "memory");                        \
    if (!_done) {                                                            \
        asm volatile(                                                        \
            "{\n\t.reg .pred P1;\n\t"                                        \
            "WAIT_LOOP_%=:\n\t"                                              \
            "mbarrier.try_wait.parity.acquire.cluster.shared::cta.b64 P1, [%0], %1, 0x989680;\n\t" \
            "@P1 bra.uni WAIT_DONE_%=;\n\t"                                  \
            "bra.uni WAIT_LOOP_%=;\n\t"                                      \
            "WAIT_DONE_%=:\n\t}"                                             \
            :: "r"(_m), "r"(_p) : "memory");                                 \
    }                                                                        \
} while (0)

// spin until *cptr >= target (acquire: producer stores then visible)
__device__ __forceinline__ void wait_cnt(const int* cptr, int target) {
    int v;
    while (true) {
        asm volatile("ld.global.acquire.gpu.b32 %0, [%1];" : "=r"(v) : "l"(cptr));
        if (v >= target) break;
        __nanosleep(64);
    }
}

__global__ void clear_prog_kernel() {
    g_prog[threadIdx.x]  = 0;
    g_hprog[threadIdx.x] = 0;
}

// =====================================================================
// MEGAKERNEL v3 — 512-thread blocks, cluster 4, dynamic smem.
//   [0, 32)      recurrence: 8 clusters x 4 CTAs, TWO batches per
//                cluster interleaved (A = 2*cid, B = 2*cid+1).
//                Weights shared across batches (registers). DSMEM/sync
//                latency of each batch hidden behind the other's compute.
//   [32, 800)    proj PAIR tiles (as R12): bump g_prog by 2 (target 6)
//   [800, 1824)  out PAIR tiles (as R12): H-part gated on g_hprog == 4
// =====================================================================
#define REC_BLOCKS  32
#define PROJ_PAIRS  768
#define OUT_PAIRS   1024

__global__ void __cluster_dims__(4, 1, 1) __launch_bounds__(512, 1)
megakernel(
    const float* __restrict__ X,
    const float* __restrict__ Wi, const float* __restrict__ bi,
    const float* __restrict__ Wf, const float* __restrict__ bf,
    const float* __restrict__ Wu, const float* __restrict__ bu,
    const float* __restrict__ Wo, const float* __restrict__ bo,
    float* __restrict__ hfinal, float* __restrict__ out)
{
    extern __shared__ char dsm[];
    const int tid = threadIdx.x;

    if (blockIdx.x < REC_BLOCKS) {
        // ========== recurrence: 4-CTA cluster, 512 thr, 2 batches ==========
        float* h_sm = (float*)dsm;                       // [4][256]: A0 A1 B0 B1
        unsigned long long* mbar = (unsigned long long*)(dsm + 4096); // [4]

        const int jj  = tid >> 3;         // local row 0..63
        const int kq  = tid & 7;          // k interleave; dest CTA = kq (<4)
        const int r   = blockIdx.x & 3;   // cluster rank
        const int cid = blockIdx.x >> 2;  // 0..7
        const int bA  = cid * 2;          // batch A; batch B = bA+1
        const int j   = r * 64 + jj;      // global row
        const int lg  = (tid & 31) & ~7;
        const size_t NSM = (size_t)NS * NM;

        // shared weights (same for both batches)
        unsigned long long wf2[16], wu2[16];
        {
            const float* pf = Wf + (size_t)j * 1280 + 1024 + 4 * kq;
            const float* pu = Wu + (size_t)j * 1280 + 1024 + 4 * kq;
            #pragma unroll
            for (int i = 0; i < 8; ++i) {
                float4 vf = *(const float4*)(pf + i * 32);
                float4 vu = *(const float4*)(pu + i * 32);
                wf2[2*i+0] = pack2(vf.x, vf.y);
                wf2[2*i+1] = pack2(vf.z, vf.w);
                wu2[2*i+0] = pack2(vu.x, vu.y);
                wu2[2*i+1] = pack2(vu.z, vu.w);
            }
        }

        // remote base address for buffer 0 slot j in CTA kq; buffers are
        // contiguous (stride 1024B), so other buffers are immediate offsets.
        uint32_t rdst0 = 0u;
        {
            const uint32_t la0 = smem_u32(&h_sm[j]);
            asm("mapa.shared::cluster.u32 %0, %1, %2;" : "=r"(rdst0) : "r"(la0), "r"(kq));
        }
        uint32_t rmb0 = 0u;   // remote mbar[0] in CTA tid (tid<4); stride 8B
        if (tid < 4) {
            const uint32_t lm0 = smem_u32(&mbar[0]);
            asm("mapa.shared::cluster.u32 %0, %1, %2;" : "=r"(rmb0) : "r"(lm0), "r"(tid));
        }
        const uint32_t hbase = smem_u32(&h_sm[4 * kq]);   // + buf*1024
        const uint32_t mloc  = smem_u32(&mbar[0]);        // + idx*8

        const size_t baseA = (size_t)bA * NSM + j;
        const bool active = (kq < 3);
        const float* pxs = (kq == 0) ? (g_xf + baseA)
                          : (kq == 1) ? (g_xu + baseA)
                          :             (g_xm + baseA);   // batch B = +NSM

        if (tid < 256) { h_sm[tid] = 0.f; h_sm[512 + tid] = 0.f; }
        if (tid == 0) {
            MBAR_INIT(mloc,      4); MBAR_INIT(mloc + 8,  4);
            MBAR_INIT(mloc + 16, 4); MBAR_INIT(mloc + 24, 4);
        }
        float hA = 0.f, hB = 0.f;
        __syncthreads();
        CLUSTER_SYNC_();

        wait_cnt(&g_prog[bA * 16], 6);
        wait_cnt(&g_prog[(bA + 1) * 16], 6);
        float vA0 = 0.f, vA1 = 0.f, vB0 = 0.f, vB1 = 0.f;
        if (active) {
            vA0 = pxs[0];   vA1 = pxs[NM];
            vB0 = pxs[NSM]; vB1 = pxs[NSM + NM];
        }

        const unsigned FULL = 0xffffffffu;
        int phA0 = 0, phA1 = 0, phB0 = 0, phB1 = 0;

        for (int t = 0; t < NS; ++t) {
            const int buf = t & 1;

            // ================= batch A half =================
            if (t > 0) {
                if (buf) { MBAR_WAIT_CL(mloc + 8, phA1); phA1 ^= 1; }
                else     { MBAR_WAIT_CL(mloc,     phA0); phA0 ^= 1; }
            }
            float hnA;
            {
                unsigned long long fa = 0ull, fb = 0ull, ua = 0ull, ub = 0ull;
                const uint32_t hb = hbase + buf * 1024;
                #pragma unroll
                for (int i = 0; i < 8; ++i) {
                    unsigned long long h01, h23;
                    asm volatile("ld.shared.v2.b64 {%0, %1}, [%2];"
                                 : "=l"(h01), "=l"(h23) : "r"(hb + i * 128));
                    FFMA2(fa, wf2[2*i+0], h01);
                    FFMA2(fb, wf2[2*i+1], h23);
                    FFMA2(ua, wu2[2*i+0], h01);
                    FFMA2(ub, wu2[2*i+1], h23);
                }
                float a0, a1, b0, b1;
                unpack2(a0, a1, fa); unpack2(b0, b1, fb);
                float af = (a0 + a1) + (b0 + b1);
                unpack2(a0, a1, ua); unpack2(b0, b1, ub);
                float au = (a0 + a1) + (b0 + b1);
                af += __shfl_xor_sync(FULL, af, 1);
                au += __shfl_xor_sync(FULL, au, 1);
                af += __shfl_xor_sync(FULL, af, 2);
                au += __shfl_xor_sync(FULL, au, 2);
                af += __shfl_xor_sync(FULL, af, 4);
                au += __shfl_xor_sync(FULL, au, 4);
                const float vc  = buf ? vA1 : vA0;
                const float xfc = __shfl_sync(FULL, vc, lg + 0);
                const float xuc = __shfl_sync(FULL, vc, lg + 1);
                const float xmc = __shfl_sync(FULL, vc, lg + 2);
                const float f = 1.f / (1.f + __expf(-(af + xfc)));
                const float u = 1.f / (1.f + __expf(-(au + xuc)));
                hnA = fmaf(f, hA, u * xmc);
                hA = hnA;
            }
            if (kq < 4 && t + 1 < NS) {
                asm volatile("st.shared::cluster.f32 [%0], %1;"
                             :: "r"(rdst0 + (buf ^ 1) * 1024), "f"(hnA) : "memory");
            }
            __syncthreads();
            if (t + 1 < NS && tid < 4) {
                asm volatile("mbarrier.arrive.release.cluster.shared::cluster.b64 _, [%0];"
                             :: "r"(rmb0 + (buf ^ 1) * 8) : "memory");
            }
            if (kq == 0) {
                g_H[baseA + (size_t)t * NM] = hnA;
                if (t == NS - 1 && hfinal) hfinal[bA * NM + j] = hnA;
            }

            // ================= batch B half =================
            if (t > 0) {
                if (buf) { MBAR_WAIT_CL(mloc + 24, phB1); phB1 ^= 1; }
                else     { MBAR_WAIT_CL(mloc + 16, phB0); phB0 ^= 1; }
            }
            float hnB;
            {
                unsigned long long fa = 0ull, fb = 0ull, ua = 0ull, ub = 0ull;
                const uint32_t hb = hbase + (2 + buf) * 1024;
                #pragma unroll
                for (int i = 0; i < 8; ++i) {
                    unsigned long long h01, h23;
                    asm volatile("ld.shared.v2.b64 {%0, %1}, [%2];"
                                 : "=l"(h01), "=l"(h23) : "r"(hb + i * 128));
                    FFMA2(fa, wf2[2*i+0], h01);
                    FFMA2(fb, wf2[2*i+1], h23);
                    FFMA2(ua, wu2[2*i+0], h01);
                    FFMA2(ub, wu2[2*i+1], h23);
                }
                float a0, a1, b0, b1;
                unpack2(a0, a1, fa); unpack2(b0, b1, fb);
                float af = (a0 + a1) + (b0 + b1);
                unpack2(a0, a1, ua); unpack2(b0, b1, ub);
                float au = (a0 + a1) + (b0 + b1);
                af += __shfl_xor_sync(FULL, af, 1);
                au += __shfl_xor_sync(FULL, au, 1);
                af += __shfl_xor_sync(FULL, af, 2);
                au += __shfl_xor_sync(FULL, au, 2);
                af += __shfl_xor_sync(FULL, af, 4);
                au += __shfl_xor_sync(FULL, au, 4);
                const float vc  = buf ? vB1 : vB0;
                const float xfc = __shfl_sync(FULL, vc, lg + 0);
                const float xuc = __shfl_sync(FULL, vc, lg + 1);
                const float xmc = __shfl_sync(FULL, vc, lg + 2);
                const float f = 1.f / (1.f + __expf(-(af + xfc)));
                const float u = 1.f / (1.f + __expf(-(au + xuc)));
                hnB = fmaf(f, hB, u * xmc);
                hB = hnB;
            }
            if (kq < 4 && t + 1 < NS) {
                asm volatile("st.shared::cluster.f32 [%0], %1;"
                             :: "r"(rdst0 + (2 + (buf ^ 1)) * 1024), "f"(hnB) : "memory");
            }
            __syncthreads();
            if (t + 1 < NS && tid < 4) {
                asm volatile("mbarrier.arrive.release.cluster.shared::cluster.b64 _, [%0];"
                             :: "r"(rmb0 + (2 + (buf ^ 1)) * 8) : "memory");
            }
            if (kq == 0) {
                g_H[baseA + NSM + (size_t)t * NM] = hnB;
                if (t == NS - 1 && hfinal) hfinal[(bA + 1) * NM + j] = hnB;
            }

            // ============ shared tail: gating, prefetch, publish ============
            if ((t & 127) == 126 && t + 2 < NS) {
                wait_cnt(&g_prog[bA * 16 + ((t + 2) >> 7)], 6);
                wait_cnt(&g_prog[(bA + 1) * 16 + ((t + 2) >> 7)], 6);
            }
            if (active && t + 2 < NS) {
                const size_t off = (size_t)(t + 2) * NM;
                const float nA = pxs[off];
                const float nB = pxs[NSM + off];
                if (buf) { vA1 = nA; vB1 = nB; }
                else     { vA0 = nA; vB0 = nB; }
            }
            if ((t & 127) == 127) {
                __threadfence();
                __syncthreads();
                if (tid == 0) {
                    asm volatile("red.release.gpu.global.add.s32 [%0], %1;"
                                 :: "l"(&g_hprog[bA * 16 + (t >> 7)]), "r"(1) : "memory");
                    asm volatile("red.release.gpu.global.add.s32 [%0], %1;"
                                 :: "l"(&g_hprog[(bA + 1) * 16 + (t >> 7)]), "r"(1) : "memory");
                }
            }
        }

        CLUSTER_SYNC_();
        return;
    }

    // =============== GEMM pair-block common setup (512 thr = 2 tiles) =======
    const int half = tid >> 8;
    const int htid = tid & 255;
    const int lane = htid & 31;
    const int warp = htid >> 5;
    const int wm   = warp >> 1;
    const int wn   = warp & 1;
    const int lr   = htid >> 2;
    const int lc   = (htid & 3) * 4;

    uint32_t* As = (uint32_t*)(dsm + DSM_AS);
    uint32_t* Bs = (uint32_t*)(dsm + DSM_BS + half * 20480);

    if (blockIdx.x < REC_BLOCKS + PROJ_PAIRS) {
        // ================= proj pair: chunk-major (c, b, seg) ================
        const int gid = blockIdx.x - REC_BLOCKS;
        const int c   = gid / 48;
        const int rem = gid - c * 48;
        const int b   = rem / 3;
        const int seg = rem - b * 3;
        const int bmrow = b * 16 + c;
        const int row0  = bmrow * 128;
        const int nbase = half * 128;

        const float* Bmat = (seg == 0) ? Wi : ((seg == 1) ? Wf : Wu);
        const int ldb     = (seg == 0) ? 1024 : 1280;
        const float* bias = (seg == 0) ? bi : ((seg == 1) ? bf : bu);
        float* dst        = (seg == 0) ? g_xm : ((seg == 1) ? g_xf : g_xu);
        const int NKT = 1024 / 16;

        float acc[2][8][4];
        #pragma unroll
        for (int i = 0; i < 2; i++)
            #pragma unroll
            for (int jx = 0; jx < 8; jx++)
                #pragma unroll
                for (int k = 0; k < 4; k++) acc[i][jx][k] = 0.f;

        float4 ra[2], rb[2];
        auto ldgA = [&](int kt) {
            const int kk = kt * 16 + lc;
            #pragma unroll
            for (int h = 0; h < 2; ++h)
                ra[h] = *(const float4*)(X + (size_t)(row0 + lr + h * 64) * ND + kk);
        };
        auto ldgB = [&](int kt) {
            const int kk = kt * 16 + lc;
            #pragma unroll
            for (int h = 0; h < 2; ++h)
                rb[h] = *(const float4*)(Bmat + (size_t)(nbase + lr + h * 64) * ldb + kk);
        };
        auto stsAB = [&](int buf) {
            #pragma unroll
            for (int h = 0; h < 2; ++h) {
                if (half == 0) {
                    uint32_t* pa = As + ((size_t)buf * 128 + lr + h * 64) * 20 + lc;
                    pa[0] = f2tf32(ra[h].x); pa[1] = f2tf32(ra[h].y);
                    pa[2] = f2tf32(ra[h].z); pa[3] = f2tf32(ra[h].w);
                }
                uint32_t* pb = Bs + ((size_t)buf * 128 + lr + h * 64) * 20 + lc;
                pb[0] = f2tf32(rb[h].x); pb[1] = f2tf32(rb[h].y);
                pb[2] = f2tf32(rb[h].z); pb[3] = f2tf32(rb[h].w);
            }
        };
        auto compute = [&](int buf) {
            #pragma unroll
            for (int ks = 0; ks < 2; ++ks) {
                const int k0 = ks * 8 + (lane & 3);
                uint32_t a[2][4]; uint32_t bb[8][2];
                #pragma unroll
                for (int mf = 0; mf < 2; ++mf) {
                    const int rr = wm * 32 + mf * 16 + (lane >> 2);
                    const uint32_t* ab = As + ((size_t)buf * 128 + rr) * 20;
                    a[mf][0] = ab[k0];
                    a[mf][1] = ab[8 * 20 + k0];
                    a[mf][2] = ab[k0 + 4];
                    a[mf][3] = ab[8 * 20 + k0 + 4];
                }
                #pragma unroll
                for (int nf = 0; nf < 8; ++nf) {
                    const int cc = wn * 64 + nf * 8 + (lane >> 2);
                    const uint32_t* bbp = Bs + ((size_t)buf * 128 + cc) * 20;
                    bb[nf][0] = bbp[k0];
                    bb[nf][1] = bbp[k0 + 4];
                }
                #pragma unroll
                for (int mf = 0; mf < 2; ++mf)
                    #pragma unroll
                    for (int nf = 0; nf < 8; ++nf)
                        mma_tf32(acc[mf][nf], a[mf], bb[nf]);
            }
        };

        if (half == 0) ldgA(0);
        ldgB(0);
        stsAB(0);
        __syncthreads();
        for (int kt = 0; kt < NKT; ++kt) {
            const int buf = kt & 1;
            if (kt + 1 < NKT) { if (half == 0) ldgA(kt + 1); ldgB(kt + 1); }
            compute(buf);
            if (kt + 1 < NKT) stsAB(buf ^ 1);
            __syncthreads();
        }

        #pragma unroll
        for (int mf = 0; mf < 2; ++mf)
            #pragma unroll
            for (int nf = 0; nf < 8; ++nf)
                #pragma unroll
                for (int h = 0; h < 2; ++h) {
                    const int row = row0 + wm * 32 + mf * 16 + (lane >> 2) + h * 8;
                    const int cl  = (nbase + wn * 64 + nf * 8 + (lane & 3) * 2) & 255;
                    float v0 = acc[mf][nf][h * 2 + 0] + bias[cl];
                    float v1 = acc[mf][nf][h * 2 + 1] + bias[cl + 1];
                    if (seg == 0) {
                        v0 = v0 / (1.f + __expf(-v0));
                        v1 = v1 / (1.f + __expf(-v1));
                    }
                    *(float2*)&dst[(size_t)row * NM + cl] = make_float2(v0, v1);
                }

        __threadfence();
        __syncthreads();
        if (tid == 0) {
            asm volatile("red.release.gpu.global.add.s32 [%0], %1;"
                         :: "l"(&g_prog[bmrow]), "r"(2) : "memory");
        }
        return;
    }

    // ============ out pair: out = x + bo + [X|H] @ Wo^T (K=1280) =============
    {
        const int gid = blockIdx.x - REC_BLOCKS - PROJ_PAIRS;
        const int c   = gid >> 6;
        const int rem = gid & 63;
        const int b   = rem >> 2;
        const int bnp = rem & 3;
        const int bm  = b * 16 + c;
        const int row0 = bm * 128;
        const int col0 = (bnp * 2 + half) * 128;
        const int NKT  = 1280 / 16;

        float acc[2][8][4];
        #pragma unroll
        for (int i = 0; i < 2; i++)
            #pragma unroll
            for (int jx = 0; jx < 8; jx++)
                #pragma unroll
                for (int k = 0; k < 4; k++) acc[i][jx][k] = 0.f;

        float4 ra[2], rb[2];
        auto ldgA = [&](int kt) {
            const int kk = kt * 16 + lc;
            #pragma unroll
            for (int h = 0; h < 2; ++h) {
                const int rr = row0 + lr + h * 64;
                if (kk >= 1024)
                    ra[h] = *(const float4*)(g_H + (size_t)rr * NM + (kk - 1024));
                else
                    ra[h] = *(const float4*)(X + (size_t)rr * ND + kk);
            }
        };
        auto ldgB = [&](int kt) {
            const int kk = kt * 16 + lc;
            #pragma unroll
            for (int h = 0; h < 2; ++h)
                rb[h] = *(const float4*)(Wo + (size_t)(col0 + lr + h * 64) * 1280 + kk);
        };
        auto stsAB = [&](int buf) {
            #pragma unroll
            for (int h = 0; h < 2; ++h) {
                if (half == 0) {
                    uint32_t* pa = As + ((size_t)buf * 128 + lr + h * 64) * 20 + lc;
                    pa[0] = f2tf32(ra[h].x); pa[1] = f2tf32(ra[h].y);
                    pa[2] = f2tf32(ra[h].z); pa[3] = f2tf32(ra[h].w);
                }
                uint32_t* pb = Bs + ((size_t)buf * 128 + lr + h * 64) * 20 + lc;
                pb[0] = f2tf32(rb[h].x); pb[1] = f2tf32(rb[h].y);
                pb[2] = f2tf32(rb[h].z); pb[3] = f2tf32(rb[h].w);
            }
        };
        auto compute = [&](int buf) {
            #pragma unroll
            for (int ks = 0; ks < 2; ++ks) {
                const int k0 = ks * 8 + (lane & 3);
                uint32_t a[2][4]; uint32_t bb[8][2];
                #pragma unroll
                for (int mf = 0; mf < 2; ++mf) {
                    const int rr = wm * 32 + mf * 16 + (lane >> 2);
                    const uint32_t* ab = As + ((size_t)buf * 128 + rr) * 20;
                    a[mf][0] = ab[k0];
                    a[mf][1] = ab[8 * 20 + k0];
                    a[mf][2] = ab[k0 + 4];
                    a[mf][3] = ab[8 * 20 + k0 + 4];
                }
                #pragma unroll
                for (int nf = 0; nf < 8; ++nf) {
                    const int cc = wn * 64 + nf * 8 + (lane >> 2);
                    const uint32_t* bbp = Bs + ((size_t)buf * 128 + cc) * 20;
                    bb[nf][0] = bbp[k0];
                    bb[nf][1] = bbp[k0 + 4];
                }
                #pragma unroll
                for (int mf = 0; mf < 2; ++mf)
                    #pragma unroll
                    for (int nf = 0; nf < 8; ++nf)
                        mma_tf32(acc[mf][nf], a[mf], bb[nf]);
            }
        };

        if (half == 0) ldgA(0);
        ldgB(0);
        stsAB(0);
        __syncthreads();
        for (int kt = 0; kt < NKT; ++kt) {
            const int buf = kt & 1;
            if (kt + 1 < NKT) {
                if (kt + 1 == 64) wait_cnt(&g_hprog[bm], 4);
                if (half == 0) ldgA(kt + 1);
                ldgB(kt + 1);
            }
            compute(buf);
            if (kt + 1 < NKT) stsAB(buf ^ 1);
            __syncthreads();
        }

        #pragma unroll
        for (int mf = 0; mf < 2; ++mf)
            #pragma unroll
            for (int nf = 0; nf < 8; ++nf)
                #pragma unroll
                for (int h = 0; h < 2; ++h) {
                    const int row = row0 + wm * 32 + mf * 16 + (lane >> 2) + h * 8;
                    const int c0  = col0 + wn * 64 + nf * 8 + (lane & 3) * 2;
                    float v0 = acc[mf][nf][h * 2 + 0] + bo[c0]     + X[(size_t)row * ND + c0];
                    float v1 = acc[mf][nf][h * 2 + 1] + bo[c0 + 1] + X[(size_t)row * ND + c0 + 1];
                    *(float2*)&out[(size_t)row * ND + c0] = make_float2(v0, v1);
                }
    }
}

// =====================================================================
extern "C" void kernel_launch(void* const* d_in, const int* in_sizes, int n_in,
                              void* d_out, int out_size)
{
    const float* x  = (const float*)d_in[0];
    const float* Wi = (const float*)d_in[1];
    const float* bi = (const float*)d_in[2];
    const float* Wf = (const float*)d_in[3];
    const float* bf = (const float*)d_in[4];
    const float* Wu = (const float*)d_in[5];
    const float* bu = (const float*)d_in[6];
    const float* Wo = (const float*)d_in[7];
    const float* bo = (const float*)d_in[8];
    float* out = (float*)d_out;

    float* hfinal = nullptr;
    if ((long long)out_size >= (long long)NROWS * ND + (long long)NB * NM)
        hfinal = out + (size_t)NROWS * ND;

    cudaFuncSetAttribute(megakernel,
                         cudaFuncAttributeMaxDynamicSharedMemorySize, DSM_TOTAL);

    clear_prog_kernel<<<1, 256>>>();
    megakernel<<<REC_BLOCKS + PROJ_PAIRS + OUT_PAIRS, 512, DSM_TOTAL>>>(
        x, Wi, bi, Wf, bf, Wu, bu, Wo, bo, hfinal, out);
}

// round 15
// speedup vs baseline: 1.6064x; 1.6064x over previous
#include <cuda_runtime.h>
#include <cstdint>
#include <cstddef>

#define NB 16
#define NS 2048
#define ND 1024
#define NM 256
#define NROWS (NB*NS)   // 32768

// ---------------- scratch (device globals: allocation-free) ----------------
__device__ __align__(16) float g_xf[(size_t)NROWS * NM];
__device__ __align__(16) float g_xu[(size_t)NROWS * NM];
__device__ __align__(16) float g_xm[(size_t)NROWS * NM];
__device__ __align__(16) float g_H [(size_t)NROWS * NM];
__device__ int g_prog [256];   // proj progress: row-block (b*16+c), target 6
__device__ int g_hprog[256];   // H progress: row-block (b*16+c), target 4

// ---------------- dynamic smem layout ----------------
// GEMM pair-blocks: As[2][128][20] @0 (20480B), Bs halves @20480/@40960
// Recurrence:       h_sm[2][256] @0 (2048B), mbar[2] @2048
#define DSM_AS    0
#define DSM_BS    20480
#define DSM_TOTAL 61440

// ---------------- helpers ----------------
__device__ __forceinline__ uint32_t f2tf32(float x) {
    uint32_t r; asm("cvt.rna.tf32.f32 %0, %1;" : "=r"(r) : "f"(x)); return r;
}
__device__ __forceinline__ void mma_tf32(float c[4], const uint32_t a[4], const uint32_t b[2]) {
    asm volatile("mma.sync.aligned.m16n8k8.row.col.f32.tf32.tf32.f32 "
        "{%0,%1,%2,%3}, {%4,%5,%6,%7}, {%8,%9}, {%0,%1,%2,%3};"
        : "+f"(c[0]), "+f"(c[1]), "+f"(c[2]), "+f"(c[3])
        : "r"(a[0]), "r"(a[1]), "r"(a[2]), "r"(a[3]), "r"(b[0]), "r"(b[1]));
}
__device__ __forceinline__ uint32_t smem_u32(const void* p) {
    return (uint32_t)__cvta_generic_to_shared(p);
}
__device__ __forceinline__ unsigned long long pack2(float lo, float hi) {
    unsigned long long r;
    asm("mov.b64 %0, {%1, %2};" : "=l"(r) : "f"(lo), "f"(hi));
    return r;
}
__device__ __forceinline__ void unpack2(float& lo, float& hi, unsigned long long v) {
    asm("mov.b64 {%0, %1}, %2;" : "=f"(lo), "=f"(hi) : "l"(v));
}
#define FFMA2(acc, a, b) \
    asm("fma.rn.f32x2 %0, %1, %2, %0;" : "+l"(acc) : "l"(a), "l"(b))

#define CLUSTER_SYNC_() do {                                          \
    asm volatile("barrier.cluster.arrive.aligned;" ::: "memory");     \
    asm volatile("barrier.cluster.wait.aligned;"   ::: "memory");     \
} while (0)

#define MBAR_INIT(addr, cnt) \
    asm volatile("mbarrier.init.shared.b64 [%0], %1;" :: "r"(addr), "r"(cnt) : "memory")

#define MBAR_WAIT_CL(addr, par) do {                                         \
    uint32_t _m = (addr); uint32_t _p = (par); uint32_t _done;               \
    asm volatile(                                                            \
        "{\n\t.reg .pred p;\n\t"                                             \
        "mbarrier.try_wait.parity.acquire.cluster.shared::cta.b64 p, [%1], %2;\n\t" \
        "selp.b32 %0, 1, 0, p;\n\t}"                                         \
        : "=r"(_done) : "r"(_m), "r"(_p) : "memory");                        \
    if (!_done) {                                                            \
        asm volatile(                                                        \
            "{\n\t.reg .pred P1;\n\t"                                        \
            "WAIT_LOOP_%=:\n\t"                                              \
            "mbarrier.try_wait.parity.acquire.cluster.shared::cta.b64 P1, [%0], %1, 0x989680;\n\t" \
            "@P1 bra.uni WAIT_DONE_%=;\n\t"                                  \
            "bra.uni WAIT_LOOP_%=;\n\t"                                      \
            "WAIT_DONE_%=:\n\t}"                                             \
            :: "r"(_m), "r"(_p) : "memory");                                 \
    }                                                                        \
} while (0)

// spin until *cptr >= target (acquire: producer stores then visible)
__device__ __forceinline__ void wait_cnt(const int* cptr, int target) {
    int v;
    while (true) {
        asm volatile("ld.global.acquire.gpu.b32 %0, [%1];" : "=r"(v) : "l"(cptr));
        if (v >= target) break;
        __nanosleep(64);
    }
}

__global__ void clear_prog_kernel() {
    g_prog[threadIdx.x]  = 0;
    g_hprog[threadIdx.x] = 0;
}

// =====================================================================
// MEGAKERNEL (R12 structure) — 512-thread blocks, cluster 4, dyn smem.
//   [0, 64)      recurrence: 16 clusters x 4 CTAs x 512 thr, 64 rows/CTA,
//                exclusive SMs. b64-paired DSMEM broadcast (rows jj,jj+1
//                packed by even-row lanes). Gated on g_prog; publishes
//                g_hprog (target 4).
//   [64, 832)    proj PAIR tiles: bump g_prog by 2 (target 6)
//   [832, 1856)  out PAIR tiles: K=1280, H-part gated on g_hprog == 4
// =====================================================================
#define REC_BLOCKS  64
#define PROJ_PAIRS  768
#define OUT_PAIRS   1024

__global__ void __cluster_dims__(4, 1, 1) __launch_bounds__(512, 1)
megakernel(
    const float* __restrict__ X,
    const float* __restrict__ Wi, const float* __restrict__ bi,
    const float* __restrict__ Wf, const float* __restrict__ bf,
    const float* __restrict__ Wu, const float* __restrict__ bu,
    const float* __restrict__ Wo, const float* __restrict__ bo,
    float* __restrict__ hfinal, float* __restrict__ out)
{
    extern __shared__ char dsm[];
    const int tid = threadIdx.x;

    if (blockIdx.x < REC_BLOCKS) {
        // ================= recurrence: 4-CTA cluster, 512 threads ===========
        float* h_sm = (float*)dsm;                          // [2][256]
        unsigned long long* mbar = (unsigned long long*)(dsm + 2048);

        const int jj = tid >> 3;          // local row 0..63
        const int kq = tid & 7;           // k interleave; dest CTA = kq (<4)
        const int r  = blockIdx.x & 3;    // cluster rank
        const int b  = blockIdx.x >> 2;   // batch
        const int j  = r * 64 + jj;       // global row
        const int lg = (tid & 31) & ~7;

        unsigned long long wf2[16], wu2[16];
        {
            const float* pf = Wf + (size_t)j * 1280 + 1024 + 4 * kq;
            const float* pu = Wu + (size_t)j * 1280 + 1024 + 4 * kq;
            #pragma unroll
            for (int i = 0; i < 8; ++i) {
                float4 vf = *(const float4*)(pf + i * 32);
                float4 vu = *(const float4*)(pu + i * 32);
                wf2[2*i+0] = pack2(vf.x, vf.y);
                wf2[2*i+1] = pack2(vf.z, vf.w);
                wu2[2*i+0] = pack2(vu.x, vu.y);
                wu2[2*i+1] = pack2(vu.z, vu.w);
            }
        }

        // remote store addresses (b64 pair base: even rows only use these)
        uint32_t rdst[2] = {0u, 0u};
        if (kq < 4) {
            const uint32_t la0 = smem_u32(&h_sm[j]);
            const uint32_t la1 = smem_u32(&h_sm[256 + j]);
            asm("mapa.shared::cluster.u32 %0, %1, %2;" : "=r"(rdst[0]) : "r"(la0), "r"(kq));
            asm("mapa.shared::cluster.u32 %0, %1, %2;" : "=r"(rdst[1]) : "r"(la1), "r"(kq));
        }
        uint32_t rmb[2] = {0u, 0u};
        if (tid < 4) {
            const uint32_t lm0 = smem_u32(&mbar[0]);
            const uint32_t lm1 = smem_u32(&mbar[1]);
            asm("mapa.shared::cluster.u32 %0, %1, %2;" : "=r"(rmb[0]) : "r"(lm0), "r"(tid));
            asm("mapa.shared::cluster.u32 %0, %1, %2;" : "=r"(rmb[1]) : "r"(lm1), "r"(tid));
        }
        const uint32_t ha[2] = { smem_u32(&h_sm[4 * kq]), smem_u32(&h_sm[256 + 4 * kq]) };

        const size_t base = (size_t)b * NS * NM + j;
        const bool active = (kq < 3);
        const float* pxs = (kq == 0) ? (g_xf + base)
                          : (kq == 1) ? (g_xu + base)
                          :             (g_xm + base);

        if (tid < 256) h_sm[tid] = 0.f;
        if (tid == 0) { MBAR_INIT(smem_u32(&mbar[0]), 4); MBAR_INIT(smem_u32(&mbar[1]), 4); }
        float h_reg = 0.f;
        __syncthreads();
        CLUSTER_SYNC_();

        wait_cnt(&g_prog[b * 16], 6);
        float v0 = 0.f, v1 = 0.f;
        if (active) { v0 = pxs[0]; v1 = pxs[NM]; }

        const unsigned FULL = 0xffffffffu;
        const uint32_t mloc[2] = { smem_u32(&mbar[0]), smem_u32(&mbar[1]) };
        int ph0 = 0, ph1 = 0;

        for (int t = 0; t < NS; ++t) {
            const int buf = t & 1;

            if (t > 0) {
                if (buf) { MBAR_WAIT_CL(mloc[1], ph1); ph1 ^= 1; }
                else     { MBAR_WAIT_CL(mloc[0], ph0); ph0 ^= 1; }
            }

            unsigned long long fa = 0ull, fb = 0ull, ua = 0ull, ub = 0ull;
            {
                const uint32_t hb = ha[buf];
                #pragma unroll
                for (int i = 0; i < 8; ++i) {
                    unsigned long long h01, h23;
                    asm volatile("ld.shared.v2.b64 {%0, %1}, [%2];"
                                 : "=l"(h01), "=l"(h23) : "r"(hb + i * 128));
                    FFMA2(fa, wf2[2*i+0], h01);
                    FFMA2(fb, wf2[2*i+1], h23);
                    FFMA2(ua, wu2[2*i+0], h01);
                    FFMA2(ub, wu2[2*i+1], h23);
                }
            }
            float f_lo, f_hi, u_lo, u_hi, t_lo, t_hi;
            unpack2(f_lo, f_hi, fa); unpack2(t_lo, t_hi, fb);
            float af = (f_lo + f_hi) + (t_lo + t_hi);
            unpack2(u_lo, u_hi, ua); unpack2(t_lo, t_hi, ub);
            float au = (u_lo + u_hi) + (t_lo + t_hi);

            af += __shfl_xor_sync(FULL, af, 1);
            au += __shfl_xor_sync(FULL, au, 1);
            af += __shfl_xor_sync(FULL, af, 2);
            au += __shfl_xor_sync(FULL, au, 2);
            af += __shfl_xor_sync(FULL, af, 4);
            au += __shfl_xor_sync(FULL, au, 4);

            const float vc  = buf ? v1 : v0;
            const float xfc = __shfl_sync(FULL, vc, lg + 0);
            const float xuc = __shfl_sync(FULL, vc, lg + 1);
            const float xmc = __shfl_sync(FULL, vc, lg + 2);

            const float f = 1.f / (1.f + __expf(-(af + xfc)));
            const float u = 1.f / (1.f + __expf(-(au + xuc)));
            const float hn = fmaf(f, h_reg, u * xmc);
            h_reg = hn;

            // neighbor row's value (rows jj / jj+1 are lanes tid^8)
            const float hn2 = __shfl_xor_sync(FULL, hn, 8);

            // ---- paired b64 broadcast: even-row lanes, dests kq<4 ----
            if (t + 1 < NS && (tid & 8) == 0 && kq < 4) {
                const unsigned long long pkt = pack2(hn, hn2);
                asm volatile("st.shared::cluster.b64 [%0], %1;"
                             :: "r"(rdst[buf ^ 1]), "l"(pkt) : "memory");
            }

            __syncthreads();   // all remote stores issued + reads of buf done

            if (t + 1 < NS && tid < 4) {
                asm volatile("mbarrier.arrive.release.cluster.shared::cluster.b64 _, [%0];"
                             :: "r"(rmb[buf ^ 1]) : "memory");
            }

            // ---- tail: paired g_H store, gating, prefetch, publish ----
            if (kq == 0 && (tid & 8) == 0) {
                *(float2*)&g_H[(size_t)(b * NS + t) * NM + j] = make_float2(hn, hn2);
                if (t == NS - 1 && hfinal)
                    *(float2*)&hfinal[b * NM + j] = make_float2(hn, hn2);
            }
            if ((t & 127) == 126 && t + 2 < NS)
                wait_cnt(&g_prog[b * 16 + ((t + 2) >> 7)], 6);
            if (active && t + 2 < NS) {
                const float nv = pxs[(size_t)(t + 2) * NM];
                if (buf) v1 = nv; else v0 = nv;
            }

            if ((t & 127) == 127) {
                __threadfence();
                __syncthreads();
                if (tid == 0) {
                    asm volatile("red.release.gpu.global.add.s32 [%0], %1;"
                                 :: "l"(&g_hprog[b * 16 + (t >> 7)]), "r"(1) : "memory");
                }
            }
        }

        CLUSTER_SYNC_();
        return;
    }

    // =============== GEMM pair-block common setup (512 thr = 2 tiles) =======
    const int half = tid >> 8;
    const int htid = tid & 255;
    const int lane = htid & 31;
    const int warp = htid >> 5;
    const int wm   = warp >> 1;
    const int wn   = warp & 1;
    const int lr   = htid >> 2;
    const int lc   = (htid & 3) * 4;

    uint32_t* As = (uint32_t*)(dsm + DSM_AS);
    uint32_t* Bs = (uint32_t*)(dsm + DSM_BS + half * 20480);

    if (blockIdx.x < REC_BLOCKS + PROJ_PAIRS) {
        // ================= proj pair: chunk-major (c, b, seg) ================
        const int gid = blockIdx.x - REC_BLOCKS;
        const int c   = gid / 48;
        const int rem = gid - c * 48;
        const int b   = rem / 3;
        const int seg = rem - b * 3;
        const int bmrow = b * 16 + c;
        const int row0  = bmrow * 128;
        const int nbase = half * 128;

        const float* Bmat = (seg == 0) ? Wi : ((seg == 1) ? Wf : Wu);
        const int ldb     = (seg == 0) ? 1024 : 1280;
        const float* bias = (seg == 0) ? bi : ((seg == 1) ? bf : bu);
        float* dst        = (seg == 0) ? g_xm : ((seg == 1) ? g_xf : g_xu);
        const int NKT = 1024 / 16;

        float acc[2][8][4];
        #pragma unroll
        for (int i = 0; i < 2; i++)
            #pragma unroll
            for (int jx = 0; jx < 8; jx++)
                #pragma unroll
                for (int k = 0; k < 4; k++) acc[i][jx][k] = 0.f;

        float4 ra[2], rb[2];
        auto ldgA = [&](int kt) {
            const int kk = kt * 16 + lc;
            #pragma unroll
            for (int h = 0; h < 2; ++h)
                ra[h] = *(const float4*)(X + (size_t)(row0 + lr + h * 64) * ND + kk);
        };
        auto ldgB = [&](int kt) {
            const int kk = kt * 16 + lc;
            #pragma unroll
            for (int h = 0; h < 2; ++h)
                rb[h] = *(const float4*)(Bmat + (size_t)(nbase + lr + h * 64) * ldb + kk);
        };
        auto stsAB = [&](int buf) {
            #pragma unroll
            for (int h = 0; h < 2; ++h) {
                if (half == 0) {
                    uint32_t* pa = As + ((size_t)buf * 128 + lr + h * 64) * 20 + lc;
                    pa[0] = f2tf32(ra[h].x); pa[1] = f2tf32(ra[h].y);
                    pa[2] = f2tf32(ra[h].z); pa[3] = f2tf32(ra[h].w);
                }
                uint32_t* pb = Bs + ((size_t)buf * 128 + lr + h * 64) * 20 + lc;
                pb[0] = f2tf32(rb[h].x); pb[1] = f2tf32(rb[h].y);
                pb[2] = f2tf32(rb[h].z); pb[3] = f2tf32(rb[h].w);
            }
        };
        auto compute = [&](int buf) {
            #pragma unroll
            for (int ks = 0; ks < 2; ++ks) {
                const int k0 = ks * 8 + (lane & 3);
                uint32_t a[2][4]; uint32_t bb[8][2];
                #pragma unroll
                for (int mf = 0; mf < 2; ++mf) {
                    const int rr = wm * 32 + mf * 16 + (lane >> 2);
                    const uint32_t* ab = As + ((size_t)buf * 128 + rr) * 20;
                    a[mf][0] = ab[k0];
                    a[mf][1] = ab[8 * 20 + k0];
                    a[mf][2] = ab[k0 + 4];
                    a[mf][3] = ab[8 * 20 + k0 + 4];
                }
                #pragma unroll
                for (int nf = 0; nf < 8; ++nf) {
                    const int cc = wn * 64 + nf * 8 + (lane >> 2);
                    const uint32_t* bbp = Bs + ((size_t)buf * 128 + cc) * 20;
                    bb[nf][0] = bbp[k0];
                    bb[nf][1] = bbp[k0 + 4];
                }
                #pragma unroll
                for (int mf = 0; mf < 2; ++mf)
                    #pragma unroll
                    for (int nf = 0; nf < 8; ++nf)
                        mma_tf32(acc[mf][nf], a[mf], bb[nf]);
            }
        };

        if (half == 0) ldgA(0);
        ldgB(0);
        stsAB(0);
        __syncthreads();
        for (int kt = 0; kt < NKT; ++kt) {
            const int buf = kt & 1;
            if (kt + 1 < NKT) { if (half == 0) ldgA(kt + 1); ldgB(kt + 1); }
            compute(buf);
            if (kt + 1 < NKT) stsAB(buf ^ 1);
            __syncthreads();
        }

        #pragma unroll
        for (int mf = 0; mf < 2; ++mf)
            #pragma unroll
            for (int nf = 0; nf < 8; ++nf)
                #pragma unroll
                for (int h = 0; h < 2; ++h) {
                    const int row = row0 + wm * 32 + mf * 16 + (lane >> 2) + h * 8;
                    const int cl  = (nbase + wn * 64 + nf * 8 + (lane & 3) * 2) & 255;
                    float v0 = acc[mf][nf][h * 2 + 0] + bias[cl];
                    float v1 = acc[mf][nf][h * 2 + 1] + bias[cl + 1];
                    if (seg == 0) {
                        v0 = v0 / (1.f + __expf(-v0));
                        v1 = v1 / (1.f + __expf(-v1));
                    }
                    *(float2*)&dst[(size_t)row * NM + cl] = make_float2(v0, v1);
                }

        __threadfence();
        __syncthreads();
        if (tid == 0) {
            asm volatile("red.release.gpu.global.add.s32 [%0], %1;"
                         :: "l"(&g_prog[bmrow]), "r"(2) : "memory");
        }
        return;
    }

    // ============ out pair: out = x + bo + [X|H] @ Wo^T (K=1280) =============
    {
        const int gid = blockIdx.x - REC_BLOCKS - PROJ_PAIRS;
        const int c   = gid >> 6;
        const int rem = gid & 63;
        const int b   = rem >> 2;
        const int bnp = rem & 3;
        const int bm  = b * 16 + c;
        const int row0 = bm * 128;
        const int col0 = (bnp * 2 + half) * 128;
        const int NKT  = 1280 / 16;

        float acc[2][8][4];
        #pragma unroll
        for (int i = 0; i < 2; i++)
            #pragma unroll
            for (int jx = 0; jx < 8; jx++)
                #pragma unroll
                for (int k = 0; k < 4; k++) acc[i][jx][k] = 0.f;

        float4 ra[2], rb[2];
        auto ldgA = [&](int kt) {
            const int kk = kt * 16 + lc;
            #pragma unroll
            for (int h = 0; h < 2; ++h) {
                const int rr = row0 + lr + h * 64;
                if (kk >= 1024)
                    ra[h] = *(const float4*)(g_H + (size_t)rr * NM + (kk - 1024));
                else
                    ra[h] = *(const float4*)(X + (size_t)rr * ND + kk);
            }
        };
        auto ldgB = [&](int kt) {
            const int kk = kt * 16 + lc;
            #pragma unroll
            for (int h = 0; h < 2; ++h)
                rb[h] = *(const float4*)(Wo + (size_t)(col0 + lr + h * 64) * 1280 + kk);
        };
        auto stsAB = [&](int buf) {
            #pragma unroll
            for (int h = 0; h < 2; ++h) {
                if (half == 0) {
                    uint32_t* pa = As + ((size_t)buf * 128 + lr + h * 64) * 20 + lc;
                    pa[0] = f2tf32(ra[h].x); pa[1] = f2tf32(ra[h].y);
                    pa[2] = f2tf32(ra[h].z); pa[3] = f2tf32(ra[h].w);
                }
                uint32_t* pb = Bs + ((size_t)buf * 128 + lr + h * 64) * 20 + lc;
                pb[0] = f2tf32(rb[h].x); pb[1] = f2tf32(rb[h].y);
                pb[2] = f2tf32(rb[h].z); pb[3] = f2tf32(rb[h].w);
            }
        };
        auto compute = [&](int buf) {
            #pragma unroll
            for (int ks = 0; ks < 2; ++ks) {
                const int k0 = ks * 8 + (lane & 3);
                uint32_t a[2][4]; uint32_t bb[8][2];
                #pragma unroll
                for (int mf = 0; mf < 2; ++mf) {
                    const int rr = wm * 32 + mf * 16 + (lane >> 2);
                    const uint32_t* ab = As + ((size_t)buf * 128 + rr) * 20;
                    a[mf][0] = ab[k0];
                    a[mf][1] = ab[8 * 20 + k0];
                    a[mf][2] = ab[k0 + 4];
                    a[mf][3] = ab[8 * 20 + k0 + 4];
                }
                #pragma unroll
                for (int nf = 0; nf < 8; ++nf) {
                    const int cc = wn * 64 + nf * 8 + (lane >> 2);
                    const uint32_t* bbp = Bs + ((size_t)buf * 128 + cc) * 20;
                    bb[nf][0] = bbp[k0];
                    bb[nf][1] = bbp[k0 + 4];
                }
                #pragma unroll
                for (int mf = 0; mf < 2; ++mf)
                    #pragma unroll
                    for (int nf = 0; nf < 8; ++nf)
                        mma_tf32(acc[mf][nf], a[mf], bb[nf]);
            }
        };

        if (half == 0) ldgA(0);
        ldgB(0);
        stsAB(0);
        __syncthreads();
        for (int kt = 0; kt < NKT; ++kt) {
            const int buf = kt & 1;
            if (kt + 1 < NKT) {
                if (kt + 1 == 64) wait_cnt(&g_hprog[bm], 4);
                if (half == 0) ldgA(kt + 1);
                ldgB(kt + 1);
            }
            compute(buf);
            if (kt + 1 < NKT) stsAB(buf ^ 1);
            __syncthreads();
        }

        #pragma unroll
        for (int mf = 0; mf < 2; ++mf)
            #pragma unroll
            for (int nf = 0; nf < 8; ++nf)
                #pragma unroll
                for (int h = 0; h < 2; ++h) {
                    const int row = row0 + wm * 32 + mf * 16 + (lane >> 2) + h * 8;
                    const int c0  = col0 + wn * 64 + nf * 8 + (lane & 3) * 2;
                    float v0 = acc[mf][nf][h * 2 + 0] + bo[c0]     + X[(size_t)row * ND + c0];
                    float v1 = acc[mf][nf][h * 2 + 1] + bo[c0 + 1] + X[(size_t)row * ND + c0 + 1];
                    *(float2*)&out[(size_t)row * ND + c0] = make_float2(v0, v1);
                }
    }
}

// =====================================================================
extern "C" void kernel_launch(void* const* d_in, const int* in_sizes, int n_in,
                              void* d_out, int out_size)
{
    const float* x  = (const float*)d_in[0];
    const float* Wi = (const float*)d_in[1];
    const float* bi = (const float*)d_in[2];
    const float* Wf = (const float*)d_in[3];
    const float* bf = (const float*)d_in[4];
    const float* Wu = (const float*)d_in[5];
    const float* bu = (const float*)d_in[6];
    const float* Wo = (const float*)d_in[7];
    const float* bo = (const float*)d_in[8];
    float* out = (float*)d_out;

    float* hfinal = nullptr;
    if ((long long)out_size >= (long long)NROWS * ND + (long long)NB * NM)
        hfinal = out + (size_t)NROWS * ND;

    cudaFuncSetAttribute(megakernel,
                         cudaFuncAttributeMaxDynamicSharedMemorySize, DSM_TOTAL);

    clear_prog_kernel<<<1, 256>>>();
    megakernel<<<REC_BLOCKS + PROJ_PAIRS + OUT_PAIRS, 512, DSM_TOTAL>>>(
        x, Wi, bi, Wf, bf, Wu, bu, Wo, bo, hfinal, out);
}